// round 10
// baseline (speedup 1.0000x reference)
#include <cuda_runtime.h>
#include <cuda_fp16.h>
#include <math.h>
#include <stdint.h>

#define NROW 8192
#define DIM  256

// ---------------- scratch (no cudaMalloc allowed) ----------------
static __device__ __half g_U   [(size_t)NROW * NROW];   // upper-tri tiles of exp(W-3)
static __device__ float  g_psum[(size_t)64 * NROW];     // per-colblock row sums
static __device__ __half g_Eh  [(size_t)NROW * DIM];    // normalized emb / sqrt(sigma)
static __device__ __half g_Vt  [(size_t)DIM * NROW];    // emb_org^T
static __device__ float  g_Opar[2][(size_t)NROW * DIM]; // split-K partial O

// ---------------- portable PTX helpers (sm_80+ only) ----------------
__device__ __forceinline__ uint32_t smem_u32(const void* p) {
    return (uint32_t)__cvta_generic_to_shared(p);
}
__device__ __forceinline__ void cp16(uint32_t dst, const void* src) {
    asm volatile("cp.async.cg.shared.global [%0], [%1], 16;"
                 :: "r"(dst), "l"(src) : "memory");
}
__device__ __forceinline__ void cp_commit() {
    asm volatile("cp.async.commit_group;" ::: "memory");
}
template <int N> __device__ __forceinline__ void cp_wait() {
    asm volatile("cp.async.wait_group %0;" :: "n"(N) : "memory");
}
__device__ __forceinline__ void ldsm4(uint32_t& r0, uint32_t& r1,
                                      uint32_t& r2, uint32_t& r3, uint32_t addr) {
    asm volatile("ldmatrix.sync.aligned.m8n8.x4.shared.b16 {%0,%1,%2,%3}, [%4];"
                 : "=r"(r0), "=r"(r1), "=r"(r2), "=r"(r3) : "r"(addr));
}
__device__ __forceinline__ void ldsm4t(uint32_t& r0, uint32_t& r1,
                                       uint32_t& r2, uint32_t& r3, uint32_t addr) {
    asm volatile("ldmatrix.sync.aligned.m8n8.x4.trans.shared.b16 {%0,%1,%2,%3}, [%4];"
                 : "=r"(r0), "=r"(r1), "=r"(r2), "=r"(r3) : "r"(addr));
}
__device__ __forceinline__ void mma16816h(float* d,
                                          uint32_t a0, uint32_t a1, uint32_t a2, uint32_t a3,
                                          uint32_t b0, uint32_t b1) {
    asm volatile("mma.sync.aligned.m16n8k16.row.col.f32.f16.f16.f32 "
                 "{%0,%1,%2,%3},{%4,%5,%6,%7},{%8,%9},{%0,%1,%2,%3};"
                 : "+f"(d[0]), "+f"(d[1]), "+f"(d[2]), "+f"(d[3])
                 : "r"(a0), "r"(a1), "r"(a2), "r"(a3), "r"(b0), "r"(b1));
}

// fast exp on the FMA pipe (avoids MUFU.EX2 wall at 67M exps).
__device__ __forceinline__ float fast_exp(float x)
{
    float t = x * 1.4426950408889634f;
    t = fmaxf(t, -126.0f);
    float fi = floorf(t);
    float f  = t - fi;
    float p = 1.5403530393381608e-4f;
    p = fmaf(p, f, 1.3333558146428443e-3f);
    p = fmaf(p, f, 9.6181291076284770e-3f);
    p = fmaf(p, f, 5.5504108664821580e-2f);
    p = fmaf(p, f, 2.4022650695910070e-1f);
    p = fmaf(p, f, 6.9314718055994530e-1f);
    p = fmaf(p, f, 1.0f);
    return p * __int_as_float(((int)fi + 127) << 23);
}

// ---------------------------------------------------------------------------
// K1: row L2-normalize (fold 1/sqrt(sigma)), write fp16.
// ---------------------------------------------------------------------------
__global__ void k_normalize(const float* __restrict__ emb)
{
    int row  = blockIdx.x * 4 + (threadIdx.x >> 5);
    int lane = threadIdx.x & 31;
    const float4* src = (const float4*)(emb + (size_t)row * DIM);
    float4 v0 = src[lane];
    float4 v1 = src[lane + 32];
    float s = v0.x*v0.x + v0.y*v0.y + v0.z*v0.z + v0.w*v0.w
            + v1.x*v1.x + v1.y*v1.y + v1.z*v1.z + v1.w*v1.w;
    #pragma unroll
    for (int o = 16; o; o >>= 1) s += __shfl_xor_sync(0xFFFFFFFFu, s, o);
    float nrm = fmaxf(sqrtf(s), 1e-12f);
    float scale = 1.0f / (nrm * 0.316227766016838f);   // 1/(norm*sqrt(sigma))
    __half2* dst = (__half2*)(g_Eh + (size_t)row * DIM);
    dst[lane * 2]            = __floats2half2_rn(v0.x * scale, v0.y * scale);
    dst[lane * 2 + 1]        = __floats2half2_rn(v0.z * scale, v0.w * scale);
    dst[(lane + 32) * 2]     = __floats2half2_rn(v1.x * scale, v1.y * scale);
    dst[(lane + 32) * 2 + 1] = __floats2half2_rn(v1.z * scale, v1.w * scale);
}

// ---------------------------------------------------------------------------
// K2: tiled transpose of V = emb_org -> Vt[c][r] fp16.
// ---------------------------------------------------------------------------
__global__ void k_transpose(const float* __restrict__ emb)
{
    __shared__ float t[32][33];
    int r0 = blockIdx.x * 32;
    int c0 = blockIdx.y * 32;
    int tx = threadIdx.x, ty = threadIdx.y;   // 32 x 8
    #pragma unroll
    for (int i = 0; i < 32; i += 8)
        t[ty + i][tx] = emb[(size_t)(r0 + ty + i) * DIM + c0 + tx];
    __syncthreads();
    #pragma unroll
    for (int i = 0; i < 32; i += 8)
        g_Vt[(size_t)(c0 + ty + i) * NROW + r0 + tx] = __float2half(t[tx][ty + i]);
}

// ---------------------------------------------------------------------------
// Shared MMA (A row-major in smem): warp tile (MI*16) x (NJB*16), k-chunk 64.
// ---------------------------------------------------------------------------
template<int MI, int NJB>
__device__ __forceinline__ void tile_mma_t(float (&acc)[MI][2 * NJB][4], int lane,
                                           int wm, int wn,
                                           uint32_t abase, uint32_t bbase)
{
    #pragma unroll
    for (int kk = 0; kk < 4; kk++) {
        uint32_t a[MI][4];
        #pragma unroll
        for (int mi = 0; mi < MI; mi++) {
            int row = wm + mi * 16 + (lane & 15);
            int k16 = 2 * kk + (lane >> 4);
            ldsm4(a[mi][0], a[mi][1], a[mi][2], a[mi][3],
                  abase + row * 128 + ((k16 ^ (row & 7)) << 4));
        }
        #pragma unroll
        for (int jb = 0; jb < NJB; jb++) {
            uint32_t b[4];
            int row = wn + jb * 16 + (lane & 7) + ((lane >> 4) << 3);
            int k16 = 2 * kk + ((lane >> 3) & 1);
            ldsm4(b[0], b[1], b[2], b[3],
                  bbase + row * 128 + ((k16 ^ (row & 7)) << 4));
            #pragma unroll
            for (int mi = 0; mi < MI; mi++) {
                mma16816h(acc[mi][jb * 2 + 0], a[mi][0], a[mi][1], a[mi][2], a[mi][3], b[0], b[1]);
                mma16816h(acc[mi][jb * 2 + 1], a[mi][0], a[mi][1], a[mi][2], a[mi][3], b[2], b[3]);
            }
        }
    }
}

// ---------------------------------------------------------------------------
// GEMM-O MMA with A row-major or TRANSPOSED ([k][m] tile via ldmatrix.trans).
// ---------------------------------------------------------------------------
template<int MI, int NJB>
__device__ __forceinline__ void tile_mma_o(float (&acc)[MI][2 * NJB][4], int lane,
                                           int wm, int wn,
                                           uint32_t abase, uint32_t bbase, int trans)
{
    #pragma unroll
    for (int kk = 0; kk < 4; kk++) {
        uint32_t a[MI][4];
        if (!trans) {
            #pragma unroll
            for (int mi = 0; mi < MI; mi++) {
                int row = wm + mi * 16 + (lane & 15);
                int k16 = 2 * kk + (lane >> 4);
                ldsm4(a[mi][0], a[mi][1], a[mi][2], a[mi][3],
                      abase + row * 128 + ((k16 ^ (row & 7)) << 4));
            }
        } else {
            #pragma unroll
            for (int mi = 0; mi < MI; mi++) {
                int srow = kk * 16 + ((lane >> 4) << 3) + (lane & 7);
                int cg = ((wm + mi * 16) >> 3) + ((lane >> 3) & 1);
                ldsm4t(a[mi][0], a[mi][1], a[mi][2], a[mi][3],
                       abase + srow * 128 + ((cg ^ (srow & 7)) << 4));
            }
        }
        #pragma unroll
        for (int jb = 0; jb < NJB; jb++) {
            uint32_t b[4];
            int row = wn + jb * 16 + (lane & 7) + ((lane >> 4) << 3);
            int k16 = 2 * kk + ((lane >> 3) & 1);
            ldsm4(b[0], b[1], b[2], b[3],
                  bbase + row * 128 + ((k16 ^ (row & 7)) << 4));
            #pragma unroll
            for (int mi = 0; mi < MI; mi++) {
                mma16816h(acc[mi][jb * 2 + 0], a[mi][0], a[mi][1], a[mi][2], a[mi][3], b[0], b[1]);
                mma16816h(acc[mi][jb * 2 + 1], a[mi][0], a[mi][1], a[mi][2], a[mi][3], b[2], b[3]);
            }
        }
    }
}

// ---------------------------------------------------------------------------
// K3: symmetric GEMM-S (triangular grid, 2080 CTAs) + fused exp epilogue.
// 2-stage cp.async pipeline, 2 CTAs/SM. Stores ONLY the upper-tri U tile.
// ---------------------------------------------------------------------------
#define SMSTAGE 32768

__device__ __forceinline__ void s_load(size_t k0, int bm0, int bn0, int tid,
                                       uint32_t stbase)
{
    uint32_t abase = stbase, bbase = stbase + 16384;
    #pragma unroll
    for (int q = 0; q < 4; q++) {
        int v = tid + q * 256;
        int row = v >> 3, k16 = v & 7;
        uint32_t off = row * 128 + ((k16 ^ (row & 7)) << 4);
        cp16(abase + off, g_Eh + (size_t)(bm0 + row) * DIM + k0 + k16 * 8);
        cp16(bbase + off, g_Eh + (size_t)(bn0 + row) * DIM + k0 + k16 * 8);
    }
    cp_commit();
}

__global__ __launch_bounds__(256, 2) void k_gemm_s()
{
    extern __shared__ __align__(1024) char dsm[];
    uint32_t dynb = smem_u32(dsm);
    int tid = threadIdx.x, lane = tid & 31, wid = tid >> 5;
    int wm = (wid >> 2) * 64, wn = (wid & 3) * 32;

    // triangular decode: t -> (i <= j)
    int t = blockIdx.x;
    int j = (int)((sqrtf(8.0f * (float)t + 1.0f) - 1.0f) * 0.5f);
    while ((j + 1) * (j + 2) / 2 <= t) j++;
    while (j * (j + 1) / 2 > t) j--;
    int i = t - j * (j + 1) / 2;
    int bm0 = i * 128, bn0 = j * 128;

    float acc[4][4][4];
    #pragma unroll
    for (int a = 0; a < 4; a++)
        #pragma unroll
        for (int b = 0; b < 4; b++)
            #pragma unroll
            for (int q = 0; q < 4; q++) acc[a][b][q] = 0.0f;

    const int NIT = 4;   // 4 chunks of 64 = K 256
    s_load(0, bm0, bn0, tid, dynb);
    for (int it = 0; it < NIT; it++) {
        int s = it & 1;
        if (it + 1 < NIT) {
            s_load((size_t)(it + 1) * 64, bm0, bn0, tid,
                   dynb + ((it + 1) & 1) * SMSTAGE);
            cp_wait<1>();
        } else {
            cp_wait<0>();
        }
        __syncthreads();
        uint32_t base = dynb + s * SMSTAGE;
        tile_mma_t<4, 2>(acc, lane, wm, wn, base, base + 16384);
        __syncthreads();
    }

    // ---- epilogue: U = exp(W - 3) ----
    int g = lane >> 2, c2 = (lane & 3) * 2;

    float pa[4], pb[4];
    #pragma unroll
    for (int mi = 0; mi < 4; mi++) { pa[mi] = 0.0f; pb[mi] = 0.0f; }
    #pragma unroll
    for (int mi = 0; mi < 4; mi++)
        #pragma unroll
        for (int nj = 0; nj < 4; nj++) {
            #pragma unroll
            for (int q = 0; q < 4; q++)
                acc[mi][nj][q] = fast_exp(acc[mi][nj][q] - 3.0f);
            pa[mi] += acc[mi][nj][0] + acc[mi][nj][1];
            pb[mi] += acc[mi][nj][2] + acc[mi][nj][3];
        }

    float* ssum = (float*)dsm;                    // [4][128]
    float* scol = (float*)(dsm + 2048);           // [2][128]
    #pragma unroll
    for (int mi = 0; mi < 4; mi++) {
        pa[mi] += __shfl_xor_sync(0xFFFFFFFFu, pa[mi], 1);
        pa[mi] += __shfl_xor_sync(0xFFFFFFFFu, pa[mi], 2);
        pb[mi] += __shfl_xor_sync(0xFFFFFFFFu, pb[mi], 1);
        pb[mi] += __shfl_xor_sync(0xFFFFFFFFu, pb[mi], 2);
        if ((lane & 3) == 0) {
            int rl = wm + mi * 16 + g;
            ssum[(wid & 3) * 128 + rl]     = pa[mi];
            ssum[(wid & 3) * 128 + rl + 8] = pb[mi];
        }
    }
    if (i != j) {
        float cs0[4], cs1[4];
        #pragma unroll
        for (int nj = 0; nj < 4; nj++) {
            cs0[nj] = 0.0f; cs1[nj] = 0.0f;
            #pragma unroll
            for (int mi = 0; mi < 4; mi++) {
                cs0[nj] += acc[mi][nj][0] + acc[mi][nj][2];
                cs1[nj] += acc[mi][nj][1] + acc[mi][nj][3];
            }
            #pragma unroll
            for (int o = 4; o <= 16; o <<= 1) {
                cs0[nj] += __shfl_xor_sync(0xFFFFFFFFu, cs0[nj], o);
                cs1[nj] += __shfl_xor_sync(0xFFFFFFFFu, cs1[nj], o);
            }
        }
        if (lane < 4) {
            #pragma unroll
            for (int nj = 0; nj < 4; nj++) {
                int col = wn + nj * 8 + lane * 2;
                scol[(wid >> 2) * 128 + col]     = cs0[nj];
                scol[(wid >> 2) * 128 + col + 1] = cs1[nj];
            }
        }
    }
    __syncthreads();
    if (tid < 128) {
        g_psum[(size_t)j * NROW + bm0 + tid] =
            ssum[tid] + ssum[128 + tid] + ssum[256 + tid] + ssum[384 + tid];
        if (i != j)
            g_psum[(size_t)i * NROW + bn0 + tid] = scol[tid] + scol[128 + tid];
    }
    __syncthreads();

    // row-major U tile store (smem-staged, coalesced) — upper triangle only.
    __half* s16 = (__half*)dsm;
    #pragma unroll
    for (int mi = 0; mi < 4; mi++)
        #pragma unroll
        for (int nj = 0; nj < 4; nj++) {
            int rl = wm + mi * 16 + g, col = wn + nj * 8 + c2;
            *(__half2*)&s16[rl * 136 + col] =
                __floats2half2_rn(acc[mi][nj][0], acc[mi][nj][1]);
            *(__half2*)&s16[(rl + 8) * 136 + col] =
                __floats2half2_rn(acc[mi][nj][2], acc[mi][nj][3]);
        }
    __syncthreads();
    {
        int rr = tid >> 1, hh = tid & 1;
        #pragma unroll
        for (int jb = 0; jb < 8; jb++) {
            uint4 v = *(uint4*)&s16[rr * 136 + hh * 64 + jb * 8];
            *(uint4*)&g_U[(size_t)(bm0 + rr) * NROW + bn0 + hh * 64 + jb * 8] = v;
        }
    }
}

// ---------------------------------------------------------------------------
// K5: O-partials, split-K x2, n-split x2.
// Grid (2, 128, 2) = 512 CTAs of 128 threads. CTA tile 64(m) x 128(n).
// 2-stage x 24KB -> 4 CTAs/SM (4 independent barriers; cross-CTA overlap).
// 4 warps (2m x 2n), warp 32x64. Mirror (trans) read for lower-tri k-blocks.
// ---------------------------------------------------------------------------
#define OSTG 24576

__device__ __forceinline__ void o_load(size_t k0, int bm0, int bn0, int tid,
                                       uint32_t base, int trans)
{
    #pragma unroll
    for (int q = 0; q < 4; q++) {
        int v = tid + q * 128;
        int row = v >> 3, k16 = v & 7;
        uint32_t off = row * 128 + ((k16 ^ (row & 7)) << 4);
        const __half* src = trans
            ? g_U + (k0 + row) * NROW + bm0 + k16 * 8           // [k][m] tile
            : g_U + (size_t)(bm0 + row) * NROW + k0 + k16 * 8;  // [m][k] tile
        cp16(base + off, src);
    }
    #pragma unroll
    for (int q = 0; q < 8; q++) {
        int v = tid + q * 128;
        int row = v >> 3, k16 = v & 7;
        uint32_t off = row * 128 + ((k16 ^ (row & 7)) << 4);
        cp16(base + 8192 + off, g_Vt + (size_t)(bn0 + row) * NROW + k0 + k16 * 8);
    }
    cp_commit();
}

__global__ __launch_bounds__(128, 4) void k_gemm_o()
{
    extern __shared__ __align__(1024) char dsm[];
    uint32_t dynb = smem_u32(dsm);
    int tid = threadIdx.x, lane = tid & 31, wid = tid >> 5;
    int wm = (wid >> 1) * 32, wn = (wid & 1) * 64;
    int bm0 = blockIdx.y * 64;
    int bn0 = blockIdx.z * 128;
    size_t kbase = (size_t)blockIdx.x * 4096;
    float* Opar = g_Opar[blockIdx.x];
    int ib = bm0 >> 7;

    float acc[2][8][4];
    #pragma unroll
    for (int a = 0; a < 2; a++)
        #pragma unroll
        for (int b = 0; b < 8; b++)
            #pragma unroll
            for (int q = 0; q < 4; q++) acc[a][b][q] = 0.0f;

    const int NIT = 64;   // K half = 4096 in chunks of 64
    {
        int tr0 = ((int)(kbase >> 7)) < ib;
        o_load(kbase, bm0, bn0, tid, dynb, tr0);
    }

    #pragma unroll 1
    for (int it = 0; it < NIT; it++) {
        int s = it & 1;
        size_t k0 = kbase + (size_t)it * 64;
        int trans = ((int)(k0 >> 7)) < ib;
        if (it + 1 < NIT) {
            size_t kn = kbase + (size_t)(it + 1) * 64;
            o_load(kn, bm0, bn0, tid, dynb + ((it + 1) & 1) * OSTG,
                   ((int)(kn >> 7)) < ib);
            cp_wait<1>();
        } else {
            cp_wait<0>();
        }
        __syncthreads();
        uint32_t base = dynb + s * OSTG;
        tile_mma_o<2, 4>(acc, lane, wm, wn, base, base + 8192, trans);
        __syncthreads();
    }

    int g = lane >> 2, c2 = (lane & 3) * 2;
    #pragma unroll
    for (int mi = 0; mi < 2; mi++) {
        int ra = bm0 + wm + mi * 16 + g;
        #pragma unroll
        for (int nj = 0; nj < 8; nj++) {
            int col = bn0 + wn + nj * 8 + c2;
            *(float2*)&Opar[(size_t)ra * DIM + col] =
                make_float2(acc[mi][nj][0], acc[mi][nj][1]);
            *(float2*)&Opar[(size_t)(ra + 8) * DIM + col] =
                make_float2(acc[mi][nj][2], acc[mi][nj][3]);
        }
    }
}

// ---------------------------------------------------------------------------
// K6: O = (Opar0 + Opar1) / rowsum.  Block = 4 rows; reduces the 64 psum
// partials per row in-block.
// ---------------------------------------------------------------------------
__global__ __launch_bounds__(256) void k_combine(float* __restrict__ C)
{
    __shared__ float sred[8];
    __shared__ float srinv[4];
    int t = threadIdx.x;
    int rowbase = blockIdx.x * 4;

    float p = g_psum[(size_t)(t & 63) * NROW + rowbase + (t >> 6)];
    #pragma unroll
    for (int o = 16; o; o >>= 1) p += __shfl_xor_sync(0xFFFFFFFFu, p, o);
    if ((t & 31) == 0) sred[t >> 5] = p;
    __syncthreads();
    if (t < 4) srinv[t] = 1.0f / (sred[2 * t] + sred[2 * t + 1]);
    __syncthreads();

    size_t idx = (size_t)blockIdx.x * 256 + t;     // float4 index
    float4 a = ((const float4*)g_Opar[0])[idx];
    float4 b = ((const float4*)g_Opar[1])[idx];
    float r = srinv[t >> 6];
    ((float4*)C)[idx] = make_float4((a.x + b.x) * r, (a.y + b.y) * r,
                                    (a.z + b.z) * r, (a.w + b.w) * r);
}

// ---------------------------------------------------------------------------
extern "C" void kernel_launch(void* const* d_in, const int* in_sizes, int n_in,
                              void* d_out, int out_size)
{
    const float* emb = (const float*)d_in[0];
    float* out = (float*)d_out;

    cudaFuncSetAttribute(k_gemm_s, cudaFuncAttributeMaxDynamicSharedMemorySize, 2 * SMSTAGE);
    cudaFuncSetAttribute(k_gemm_o, cudaFuncAttributeMaxDynamicSharedMemorySize, 2 * OSTG);

    k_normalize<<<NROW / 4, 128>>>(emb);

    dim3 tb(32, 8);
    k_transpose<<<dim3(NROW / 32, DIM / 32), tb>>>(emb);

    k_gemm_s<<<2080, 256, 2 * SMSTAGE>>>();

    k_gemm_o<<<dim3(2, NROW / 64, 2), 128, 2 * OSTG>>>();

    k_combine<<<NROW / 4, 256>>>(out);
}

// round 12
// speedup vs baseline: 1.0438x; 1.0438x over previous
#include <cuda_runtime.h>
#include <cuda_fp16.h>
#include <math.h>
#include <stdint.h>

#define NROW 8192
#define DIM  256

// ---------------- scratch (no cudaMalloc allowed) ----------------
static __device__ __half g_U   [(size_t)NROW * NROW];   // upper-tri tiles of exp(W-3)
static __device__ float  g_psum[(size_t)64 * NROW];     // per-colblock row sums
static __device__ __half g_Eh  [(size_t)NROW * DIM];    // normalized emb / sqrt(sigma)
static __device__ __half g_Vt  [(size_t)DIM * NROW];    // emb_org^T
static __device__ float  g_Opar[2][(size_t)NROW * DIM]; // split-K partial O

// ---------------- portable PTX helpers (sm_80+ only) ----------------
__device__ __forceinline__ uint32_t smem_u32(const void* p) {
    return (uint32_t)__cvta_generic_to_shared(p);
}
__device__ __forceinline__ void cp16(uint32_t dst, const void* src) {
    asm volatile("cp.async.cg.shared.global [%0], [%1], 16;"
                 :: "r"(dst), "l"(src) : "memory");
}
__device__ __forceinline__ void cp_commit() {
    asm volatile("cp.async.commit_group;" ::: "memory");
}
template <int N> __device__ __forceinline__ void cp_wait() {
    asm volatile("cp.async.wait_group %0;" :: "n"(N) : "memory");
}
__device__ __forceinline__ void ldsm4(uint32_t& r0, uint32_t& r1,
                                      uint32_t& r2, uint32_t& r3, uint32_t addr) {
    asm volatile("ldmatrix.sync.aligned.m8n8.x4.shared.b16 {%0,%1,%2,%3}, [%4];"
                 : "=r"(r0), "=r"(r1), "=r"(r2), "=r"(r3) : "r"(addr));
}
__device__ __forceinline__ void ldsm4t(uint32_t& r0, uint32_t& r1,
                                       uint32_t& r2, uint32_t& r3, uint32_t addr) {
    asm volatile("ldmatrix.sync.aligned.m8n8.x4.trans.shared.b16 {%0,%1,%2,%3}, [%4];"
                 : "=r"(r0), "=r"(r1), "=r"(r2), "=r"(r3) : "r"(addr));
}
__device__ __forceinline__ void mma16816h(float* d,
                                          uint32_t a0, uint32_t a1, uint32_t a2, uint32_t a3,
                                          uint32_t b0, uint32_t b1) {
    asm volatile("mma.sync.aligned.m16n8k16.row.col.f32.f16.f16.f32 "
                 "{%0,%1,%2,%3},{%4,%5,%6,%7},{%8,%9},{%0,%1,%2,%3};"
                 : "+f"(d[0]), "+f"(d[1]), "+f"(d[2]), "+f"(d[3])
                 : "r"(a0), "r"(a1), "r"(a2), "r"(a3), "r"(b0), "r"(b1));
}

// fast exp on the FMA pipe (avoids MUFU.EX2 wall at 67M exps).
__device__ __forceinline__ float fast_exp(float x)
{
    float t = x * 1.4426950408889634f;
    t = fmaxf(t, -126.0f);
    float fi = floorf(t);
    float f  = t - fi;
    float p = 1.5403530393381608e-4f;
    p = fmaf(p, f, 1.3333558146428443e-3f);
    p = fmaf(p, f, 9.6181291076284770e-3f);
    p = fmaf(p, f, 5.5504108664821580e-2f);
    p = fmaf(p, f, 2.4022650695910070e-1f);
    p = fmaf(p, f, 6.9314718055994530e-1f);
    p = fmaf(p, f, 1.0f);
    return p * __int_as_float(((int)fi + 127) << 23);
}

// ---------------------------------------------------------------------------
// K1: row L2-normalize (fold 1/sqrt(sigma)), write fp16.
// ---------------------------------------------------------------------------
__global__ void k_normalize(const float* __restrict__ emb)
{
    int row  = blockIdx.x * 4 + (threadIdx.x >> 5);
    int lane = threadIdx.x & 31;
    const float4* src = (const float4*)(emb + (size_t)row * DIM);
    float4 v0 = src[lane];
    float4 v1 = src[lane + 32];
    float s = v0.x*v0.x + v0.y*v0.y + v0.z*v0.z + v0.w*v0.w
            + v1.x*v1.x + v1.y*v1.y + v1.z*v1.z + v1.w*v1.w;
    #pragma unroll
    for (int o = 16; o; o >>= 1) s += __shfl_xor_sync(0xFFFFFFFFu, s, o);
    float nrm = fmaxf(sqrtf(s), 1e-12f);
    float scale = 1.0f / (nrm * 0.316227766016838f);   // 1/(norm*sqrt(sigma))
    __half2* dst = (__half2*)(g_Eh + (size_t)row * DIM);
    dst[lane * 2]            = __floats2half2_rn(v0.x * scale, v0.y * scale);
    dst[lane * 2 + 1]        = __floats2half2_rn(v0.z * scale, v0.w * scale);
    dst[(lane + 32) * 2]     = __floats2half2_rn(v1.x * scale, v1.y * scale);
    dst[(lane + 32) * 2 + 1] = __floats2half2_rn(v1.z * scale, v1.w * scale);
}

// ---------------------------------------------------------------------------
// K2: tiled transpose of V = emb_org -> Vt[c][r] fp16.
// ---------------------------------------------------------------------------
__global__ void k_transpose(const float* __restrict__ emb)
{
    __shared__ float t[32][33];
    int r0 = blockIdx.x * 32;
    int c0 = blockIdx.y * 32;
    int tx = threadIdx.x, ty = threadIdx.y;   // 32 x 8
    #pragma unroll
    for (int i = 0; i < 32; i += 8)
        t[ty + i][tx] = emb[(size_t)(r0 + ty + i) * DIM + c0 + tx];
    __syncthreads();
    #pragma unroll
    for (int i = 0; i < 32; i += 8)
        g_Vt[(size_t)(c0 + ty + i) * NROW + r0 + tx] = __float2half(t[tx][ty + i]);
}

// ---------------------------------------------------------------------------
// Shared MMA (A row-major in smem): warp tile (MI*16) x (NJB*16), k-chunk 64.
// ---------------------------------------------------------------------------
template<int MI, int NJB>
__device__ __forceinline__ void tile_mma_t(float (&acc)[MI][2 * NJB][4], int lane,
                                           int wm, int wn,
                                           uint32_t abase, uint32_t bbase)
{
    #pragma unroll
    for (int kk = 0; kk < 4; kk++) {
        uint32_t a[MI][4];
        #pragma unroll
        for (int mi = 0; mi < MI; mi++) {
            int row = wm + mi * 16 + (lane & 15);
            int k16 = 2 * kk + (lane >> 4);
            ldsm4(a[mi][0], a[mi][1], a[mi][2], a[mi][3],
                  abase + row * 128 + ((k16 ^ (row & 7)) << 4));
        }
        #pragma unroll
        for (int jb = 0; jb < NJB; jb++) {
            uint32_t b[4];
            int row = wn + jb * 16 + (lane & 7) + ((lane >> 4) << 3);
            int k16 = 2 * kk + ((lane >> 3) & 1);
            ldsm4(b[0], b[1], b[2], b[3],
                  bbase + row * 128 + ((k16 ^ (row & 7)) << 4));
            #pragma unroll
            for (int mi = 0; mi < MI; mi++) {
                mma16816h(acc[mi][jb * 2 + 0], a[mi][0], a[mi][1], a[mi][2], a[mi][3], b[0], b[1]);
                mma16816h(acc[mi][jb * 2 + 1], a[mi][0], a[mi][1], a[mi][2], a[mi][3], b[2], b[3]);
            }
        }
    }
}

// ---------------------------------------------------------------------------
// GEMM-O MMA. A either row-major [m=128][k=64] (128 B rows) or TRANSPOSED:
// mirrored U stored as TWO [k=64][m=64] sub-tiles (m-half h at +h*8192,
// 128 B rows), consumed via ldmatrix.x4.trans:
//   srow = kk*16 + 8*(lane>>4) + (lane&7)
//   cg   = ((m_off & 63) >> 3) + ((lane>>3)&1),  base += (m_off>>6)*8192
// ---------------------------------------------------------------------------
template<int MI, int NJB>
__device__ __forceinline__ void tile_mma_o(float (&acc)[MI][2 * NJB][4], int lane,
                                           int wm, int wn,
                                           uint32_t abase, uint32_t bbase, int trans)
{
    #pragma unroll
    for (int kk = 0; kk < 4; kk++) {
        uint32_t a[MI][4];
        if (!trans) {
            #pragma unroll
            for (int mi = 0; mi < MI; mi++) {
                int row = wm + mi * 16 + (lane & 15);
                int k16 = 2 * kk + (lane >> 4);
                ldsm4(a[mi][0], a[mi][1], a[mi][2], a[mi][3],
                      abase + row * 128 + ((k16 ^ (row & 7)) << 4));
            }
        } else {
            #pragma unroll
            for (int mi = 0; mi < MI; mi++) {
                int m_off = wm + mi * 16;
                uint32_t mh = (uint32_t)(m_off >> 6) * 8192u;
                int srow = kk * 16 + ((lane >> 4) << 3) + (lane & 7);
                int cg = ((m_off & 63) >> 3) + ((lane >> 3) & 1);
                ldsm4t(a[mi][0], a[mi][1], a[mi][2], a[mi][3],
                       abase + mh + srow * 128 + ((cg ^ (srow & 7)) << 4));
            }
        }
        #pragma unroll
        for (int jb = 0; jb < NJB; jb++) {
            uint32_t b[4];
            int row = wn + jb * 16 + (lane & 7) + ((lane >> 4) << 3);
            int k16 = 2 * kk + ((lane >> 3) & 1);
            ldsm4(b[0], b[1], b[2], b[3],
                  bbase + row * 128 + ((k16 ^ (row & 7)) << 4));
            #pragma unroll
            for (int mi = 0; mi < MI; mi++) {
                mma16816h(acc[mi][jb * 2 + 0], a[mi][0], a[mi][1], a[mi][2], a[mi][3], b[0], b[1]);
                mma16816h(acc[mi][jb * 2 + 1], a[mi][0], a[mi][1], a[mi][2], a[mi][3], b[2], b[3]);
            }
        }
    }
}

// ---------------------------------------------------------------------------
// K3: symmetric GEMM-S (triangular grid, 2080 CTAs) + fused exp epilogue.
// 2-stage cp.async pipeline, 2 CTAs/SM. Stores ONLY the upper-tri U tile.
// ---------------------------------------------------------------------------
#define SMSTAGE 32768

__device__ __forceinline__ void s_load(size_t k0, int bm0, int bn0, int tid,
                                       uint32_t stbase)
{
    uint32_t abase = stbase, bbase = stbase + 16384;
    #pragma unroll
    for (int q = 0; q < 4; q++) {
        int v = tid + q * 256;
        int row = v >> 3, k16 = v & 7;
        uint32_t off = row * 128 + ((k16 ^ (row & 7)) << 4);
        cp16(abase + off, g_Eh + (size_t)(bm0 + row) * DIM + k0 + k16 * 8);
        cp16(bbase + off, g_Eh + (size_t)(bn0 + row) * DIM + k0 + k16 * 8);
    }
    cp_commit();
}

__global__ __launch_bounds__(256, 2) void k_gemm_s()
{
    extern __shared__ __align__(1024) char dsm[];
    uint32_t dynb = smem_u32(dsm);
    int tid = threadIdx.x, lane = tid & 31, wid = tid >> 5;
    int wm = (wid >> 2) * 64, wn = (wid & 3) * 32;

    // triangular decode: t -> (i <= j)
    int t = blockIdx.x;
    int j = (int)((sqrtf(8.0f * (float)t + 1.0f) - 1.0f) * 0.5f);
    while ((j + 1) * (j + 2) / 2 <= t) j++;
    while (j * (j + 1) / 2 > t) j--;
    int i = t - j * (j + 1) / 2;
    int bm0 = i * 128, bn0 = j * 128;

    float acc[4][4][4];
    #pragma unroll
    for (int a = 0; a < 4; a++)
        #pragma unroll
        for (int b = 0; b < 4; b++)
            #pragma unroll
            for (int q = 0; q < 4; q++) acc[a][b][q] = 0.0f;

    const int NIT = 4;   // 4 chunks of 64 = K 256
    s_load(0, bm0, bn0, tid, dynb);
    for (int it = 0; it < NIT; it++) {
        int s = it & 1;
        if (it + 1 < NIT) {
            s_load((size_t)(it + 1) * 64, bm0, bn0, tid,
                   dynb + ((it + 1) & 1) * SMSTAGE);
            cp_wait<1>();
        } else {
            cp_wait<0>();
        }
        __syncthreads();
        uint32_t base = dynb + s * SMSTAGE;
        tile_mma_t<4, 2>(acc, lane, wm, wn, base, base + 16384);
        __syncthreads();
    }

    // ---- epilogue: U = exp(W - 3) ----
    int g = lane >> 2, c2 = (lane & 3) * 2;

    float pa[4], pb[4];
    #pragma unroll
    for (int mi = 0; mi < 4; mi++) { pa[mi] = 0.0f; pb[mi] = 0.0f; }
    #pragma unroll
    for (int mi = 0; mi < 4; mi++)
        #pragma unroll
        for (int nj = 0; nj < 4; nj++) {
            #pragma unroll
            for (int q = 0; q < 4; q++)
                acc[mi][nj][q] = fast_exp(acc[mi][nj][q] - 3.0f);
            pa[mi] += acc[mi][nj][0] + acc[mi][nj][1];
            pb[mi] += acc[mi][nj][2] + acc[mi][nj][3];
        }

    float* ssum = (float*)dsm;                    // [4][128]
    float* scol = (float*)(dsm + 2048);           // [2][128]
    #pragma unroll
    for (int mi = 0; mi < 4; mi++) {
        pa[mi] += __shfl_xor_sync(0xFFFFFFFFu, pa[mi], 1);
        pa[mi] += __shfl_xor_sync(0xFFFFFFFFu, pa[mi], 2);
        pb[mi] += __shfl_xor_sync(0xFFFFFFFFu, pb[mi], 1);
        pb[mi] += __shfl_xor_sync(0xFFFFFFFFu, pb[mi], 2);
        if ((lane & 3) == 0) {
            int rl = wm + mi * 16 + g;
            ssum[(wid & 3) * 128 + rl]     = pa[mi];
            ssum[(wid & 3) * 128 + rl + 8] = pb[mi];
        }
    }
    if (i != j) {
        float cs0[4], cs1[4];
        #pragma unroll
        for (int nj = 0; nj < 4; nj++) {
            cs0[nj] = 0.0f; cs1[nj] = 0.0f;
            #pragma unroll
            for (int mi = 0; mi < 4; mi++) {
                cs0[nj] += acc[mi][nj][0] + acc[mi][nj][2];
                cs1[nj] += acc[mi][nj][1] + acc[mi][nj][3];
            }
            #pragma unroll
            for (int o = 4; o <= 16; o <<= 1) {
                cs0[nj] += __shfl_xor_sync(0xFFFFFFFFu, cs0[nj], o);
                cs1[nj] += __shfl_xor_sync(0xFFFFFFFFu, cs1[nj], o);
            }
        }
        if (lane < 4) {
            #pragma unroll
            for (int nj = 0; nj < 4; nj++) {
                int col = wn + nj * 8 + lane * 2;
                scol[(wid >> 2) * 128 + col]     = cs0[nj];
                scol[(wid >> 2) * 128 + col + 1] = cs1[nj];
            }
        }
    }
    __syncthreads();
    if (tid < 128) {
        g_psum[(size_t)j * NROW + bm0 + tid] =
            ssum[tid] + ssum[128 + tid] + ssum[256 + tid] + ssum[384 + tid];
        if (i != j)
            g_psum[(size_t)i * NROW + bn0 + tid] = scol[tid] + scol[128 + tid];
    }
    __syncthreads();

    // row-major U tile store (smem-staged, coalesced) — upper triangle only.
    __half* s16 = (__half*)dsm;
    #pragma unroll
    for (int mi = 0; mi < 4; mi++)
        #pragma unroll
        for (int nj = 0; nj < 4; nj++) {
            int rl = wm + mi * 16 + g, col = wn + nj * 8 + c2;
            *(__half2*)&s16[rl * 136 + col] =
                __floats2half2_rn(acc[mi][nj][0], acc[mi][nj][1]);
            *(__half2*)&s16[(rl + 8) * 136 + col] =
                __floats2half2_rn(acc[mi][nj][2], acc[mi][nj][3]);
        }
    __syncthreads();
    {
        int rr = tid >> 1, hh = tid & 1;
        #pragma unroll
        for (int jb = 0; jb < 8; jb++) {
            uint4 v = *(uint4*)&s16[rr * 136 + hh * 64 + jb * 8];
            *(uint4*)&g_U[(size_t)(bm0 + rr) * NROW + bn0 + hh * 64 + jb * 8] = v;
        }
    }
}

// ---------------------------------------------------------------------------
// K5: O-partials, split-K x2, n-split x2.
// Grid (2, 64, 2) = 256 CTAs of 128 threads. CTA tile 128(m) x 128(n).
// 4 warps of 64x64 (MI=4, NJB=4): 128 B smem reads / mma (vs 192 before).
// 3-stage x 32KB = 96KB -> 2 CTAs/SM. Mirror (trans) read for lower-tri
// k-blocks, stored as two [64k][64m] sub-tiles (+0 / +8192).
// ---------------------------------------------------------------------------
#define OSTG 32768

__device__ __forceinline__ void o_load(size_t k0, int bm0, int bn0, int tid,
                                       uint32_t base, int trans)
{
    if (trans) {
        #pragma unroll
        for (int q = 0; q < 8; q++) {
            int v = tid + q * 128;                  // 0..1023
            uint32_t mh  = (uint32_t)(v >> 9);      // m-half 0/1
            int within   = v & 511;
            int row      = within >> 3;             // k row 0..63
            int k16      = within & 7;              // m 16B group within half
            uint32_t off = mh * 8192 + row * 128 + ((k16 ^ (row & 7)) << 4);
            cp16(base + off,
                 g_U + (k0 + row) * NROW + bm0 + mh * 64 + k16 * 8);
            // V tile (unchanged layout)
            int vrow = v >> 3, vk = v & 7;
            cp16(base + 16384 + vrow * 128 + ((vk ^ (vrow & 7)) << 4),
                 g_Vt + (size_t)(bn0 + vrow) * NROW + k0 + vk * 8);
        }
    } else {
        #pragma unroll
        for (int q = 0; q < 8; q++) {
            int v = tid + q * 128;
            int row = v >> 3, k16 = v & 7;
            uint32_t off = row * 128 + ((k16 ^ (row & 7)) << 4);
            cp16(base + off, g_U + (size_t)(bm0 + row) * NROW + k0 + k16 * 8);
            cp16(base + 16384 + off,
                 g_Vt + (size_t)(bn0 + row) * NROW + k0 + k16 * 8);
        }
    }
    cp_commit();
}

__global__ __launch_bounds__(128, 2) void k_gemm_o()
{
    extern __shared__ __align__(1024) char dsm[];
    uint32_t dynb = smem_u32(dsm);
    int tid = threadIdx.x, lane = tid & 31, wid = tid >> 5;
    int wm = (wid >> 1) * 64, wn = (wid & 1) * 64;
    int bm0 = blockIdx.y * 128;
    int bn0 = blockIdx.z * 128;
    size_t kbase = (size_t)blockIdx.x * 4096;
    float* Opar = g_Opar[blockIdx.x];
    int ib = bm0 >> 7;

    float acc[4][8][4];
    #pragma unroll
    for (int a = 0; a < 4; a++)
        #pragma unroll
        for (int b = 0; b < 8; b++)
            #pragma unroll
            for (int q = 0; q < 4; q++) acc[a][b][q] = 0.0f;

    const int NIT = 64;   // K half = 4096 in chunks of 64
    {
        int tr0 = ((int)(kbase >> 7)) < ib;
        o_load(kbase, bm0, bn0, tid, dynb, tr0);
        size_t k1 = kbase + 64;
        o_load(k1, bm0, bn0, tid, dynb + OSTG, ((int)(k1 >> 7)) < ib);
    }

    #pragma unroll 1
    for (int it = 0; it < NIT; it++) {
        int s = it % 3;
        size_t k0 = kbase + (size_t)it * 64;
        int trans = ((int)(k0 >> 7)) < ib;
        if (it + 2 < NIT) {
            size_t kn = kbase + (size_t)(it + 2) * 64;
            o_load(kn, bm0, bn0, tid, dynb + ((it + 2) % 3) * OSTG,
                   ((int)(kn >> 7)) < ib);
            cp_wait<2>();
        } else {
            cp_wait<0>();
        }
        __syncthreads();
        uint32_t base = dynb + s * OSTG;
        tile_mma_o<4, 4>(acc, lane, wm, wn, base, base + 16384, trans);
        __syncthreads();
    }

    int g = lane >> 2, c2 = (lane & 3) * 2;
    #pragma unroll
    for (int mi = 0; mi < 4; mi++) {
        int ra = bm0 + wm + mi * 16 + g;
        #pragma unroll
        for (int nj = 0; nj < 8; nj++) {
            int col = bn0 + wn + nj * 8 + c2;
            *(float2*)&Opar[(size_t)ra * DIM + col] =
                make_float2(acc[mi][nj][0], acc[mi][nj][1]);
            *(float2*)&Opar[(size_t)(ra + 8) * DIM + col] =
                make_float2(acc[mi][nj][2], acc[mi][nj][3]);
        }
    }
}

// ---------------------------------------------------------------------------
// K6: O = (Opar0 + Opar1) / rowsum.  Block = 4 rows; reduces the 64 psum
// partials per row in-block.
// ---------------------------------------------------------------------------
__global__ __launch_bounds__(256) void k_combine(float* __restrict__ C)
{
    __shared__ float sred[8];
    __shared__ float srinv[4];
    int t = threadIdx.x;
    int rowbase = blockIdx.x * 4;

    float p = g_psum[(size_t)(t & 63) * NROW + rowbase + (t >> 6)];
    #pragma unroll
    for (int o = 16; o; o >>= 1) p += __shfl_xor_sync(0xFFFFFFFFu, p, o);
    if ((t & 31) == 0) sred[t >> 5] = p;
    __syncthreads();
    if (t < 4) srinv[t] = 1.0f / (sred[2 * t] + sred[2 * t + 1]);
    __syncthreads();

    size_t idx = (size_t)blockIdx.x * 256 + t;     // float4 index
    float4 a = ((const float4*)g_Opar[0])[idx];
    float4 b = ((const float4*)g_Opar[1])[idx];
    float r = srinv[t >> 6];
    ((float4*)C)[idx] = make_float4((a.x + b.x) * r, (a.y + b.y) * r,
                                    (a.z + b.z) * r, (a.w + b.w) * r);
}

// ---------------------------------------------------------------------------
extern "C" void kernel_launch(void* const* d_in, const int* in_sizes, int n_in,
                              void* d_out, int out_size)
{
    const float* emb = (const float*)d_in[0];
    float* out = (float*)d_out;

    cudaFuncSetAttribute(k_gemm_s, cudaFuncAttributeMaxDynamicSharedMemorySize, 2 * SMSTAGE);
    cudaFuncSetAttribute(k_gemm_o, cudaFuncAttributeMaxDynamicSharedMemorySize, 3 * OSTG);

    k_normalize<<<NROW / 4, 128>>>(emb);

    dim3 tb(32, 8);
    k_transpose<<<dim3(NROW / 32, DIM / 32), tb>>>(emb);

    k_gemm_s<<<2080, 256, 2 * SMSTAGE>>>();

    k_gemm_o<<<dim3(2, NROW / 128, 2), 128, 3 * OSTG>>>();

    k_combine<<<NROW / 4, 256>>>(out);
}

// round 13
// speedup vs baseline: 1.0477x; 1.0038x over previous
#include <cuda_runtime.h>
#include <cuda_fp16.h>
#include <math.h>
#include <stdint.h>

#define NROW 8192
#define DIM  256

// ---------------- scratch (no cudaMalloc allowed) ----------------
static __device__ __half g_U   [(size_t)NROW * NROW];   // upper-tri tiles of exp(W-3)
static __device__ float  g_psum[(size_t)64 * NROW];     // per-colblock row sums
static __device__ __half g_Eh  [(size_t)NROW * DIM];    // normalized emb / sqrt(sigma)
static __device__ __half g_Vt  [(size_t)DIM * NROW];    // emb_org^T
static __device__ float  g_Opar[2][(size_t)NROW * DIM]; // split-K partial O

// ---------------- portable PTX helpers (sm_80+ only) ----------------
__device__ __forceinline__ uint32_t smem_u32(const void* p) {
    return (uint32_t)__cvta_generic_to_shared(p);
}
__device__ __forceinline__ void cp16(uint32_t dst, const void* src) {
    asm volatile("cp.async.cg.shared.global [%0], [%1], 16;"
                 :: "r"(dst), "l"(src) : "memory");
}
__device__ __forceinline__ void cp_commit() {
    asm volatile("cp.async.commit_group;" ::: "memory");
}
template <int N> __device__ __forceinline__ void cp_wait() {
    asm volatile("cp.async.wait_group %0;" :: "n"(N) : "memory");
}
__device__ __forceinline__ void ldsm4(uint32_t& r0, uint32_t& r1,
                                      uint32_t& r2, uint32_t& r3, uint32_t addr) {
    asm volatile("ldmatrix.sync.aligned.m8n8.x4.shared.b16 {%0,%1,%2,%3}, [%4];"
                 : "=r"(r0), "=r"(r1), "=r"(r2), "=r"(r3) : "r"(addr));
}
__device__ __forceinline__ void ldsm4t(uint32_t& r0, uint32_t& r1,
                                       uint32_t& r2, uint32_t& r3, uint32_t addr) {
    asm volatile("ldmatrix.sync.aligned.m8n8.x4.trans.shared.b16 {%0,%1,%2,%3}, [%4];"
                 : "=r"(r0), "=r"(r1), "=r"(r2), "=r"(r3) : "r"(addr));
}
__device__ __forceinline__ void mma16816h(float* d,
                                          uint32_t a0, uint32_t a1, uint32_t a2, uint32_t a3,
                                          uint32_t b0, uint32_t b1) {
    asm volatile("mma.sync.aligned.m16n8k16.row.col.f32.f16.f16.f32 "
                 "{%0,%1,%2,%3},{%4,%5,%6,%7},{%8,%9},{%0,%1,%2,%3};"
                 : "+f"(d[0]), "+f"(d[1]), "+f"(d[2]), "+f"(d[3])
                 : "r"(a0), "r"(a1), "r"(a2), "r"(a3), "r"(b0), "r"(b1));
}

// fast exp on the FMA pipe (avoids MUFU.EX2 wall at 67M exps).
__device__ __forceinline__ float fast_exp(float x)
{
    float t = x * 1.4426950408889634f;
    t = fmaxf(t, -126.0f);
    float fi = floorf(t);
    float f  = t - fi;
    float p = 1.5403530393381608e-4f;
    p = fmaf(p, f, 1.3333558146428443e-3f);
    p = fmaf(p, f, 9.6181291076284770e-3f);
    p = fmaf(p, f, 5.5504108664821580e-2f);
    p = fmaf(p, f, 2.4022650695910070e-1f);
    p = fmaf(p, f, 6.9314718055994530e-1f);
    p = fmaf(p, f, 1.0f);
    return p * __int_as_float(((int)fi + 127) << 23);
}

// ---------------------------------------------------------------------------
// K1: row L2-normalize (fold 1/sqrt(sigma)), write fp16.
// ---------------------------------------------------------------------------
__global__ void k_normalize(const float* __restrict__ emb)
{
    int row  = blockIdx.x * 4 + (threadIdx.x >> 5);
    int lane = threadIdx.x & 31;
    const float4* src = (const float4*)(emb + (size_t)row * DIM);
    float4 v0 = src[lane];
    float4 v1 = src[lane + 32];
    float s = v0.x*v0.x + v0.y*v0.y + v0.z*v0.z + v0.w*v0.w
            + v1.x*v1.x + v1.y*v1.y + v1.z*v1.z + v1.w*v1.w;
    #pragma unroll
    for (int o = 16; o; o >>= 1) s += __shfl_xor_sync(0xFFFFFFFFu, s, o);
    float nrm = fmaxf(sqrtf(s), 1e-12f);
    float scale = 1.0f / (nrm * 0.316227766016838f);   // 1/(norm*sqrt(sigma))
    __half2* dst = (__half2*)(g_Eh + (size_t)row * DIM);
    dst[lane * 2]            = __floats2half2_rn(v0.x * scale, v0.y * scale);
    dst[lane * 2 + 1]        = __floats2half2_rn(v0.z * scale, v0.w * scale);
    dst[(lane + 32) * 2]     = __floats2half2_rn(v1.x * scale, v1.y * scale);
    dst[(lane + 32) * 2 + 1] = __floats2half2_rn(v1.z * scale, v1.w * scale);
}

// ---------------------------------------------------------------------------
// K2: tiled transpose of V = emb_org -> Vt[c][r] fp16.
// ---------------------------------------------------------------------------
__global__ void k_transpose(const float* __restrict__ emb)
{
    __shared__ float t[32][33];
    int r0 = blockIdx.x * 32;
    int c0 = blockIdx.y * 32;
    int tx = threadIdx.x, ty = threadIdx.y;   // 32 x 8
    #pragma unroll
    for (int i = 0; i < 32; i += 8)
        t[ty + i][tx] = emb[(size_t)(r0 + ty + i) * DIM + c0 + tx];
    __syncthreads();
    #pragma unroll
    for (int i = 0; i < 32; i += 8)
        g_Vt[(size_t)(c0 + ty + i) * NROW + r0 + tx] = __float2half(t[tx][ty + i]);
}

// ---------------------------------------------------------------------------
// Shared MMA (A row-major in smem): warp tile (MI*16) x (NJB*16), k-chunk 64.
// ---------------------------------------------------------------------------
template<int MI, int NJB>
__device__ __forceinline__ void tile_mma_t(float (&acc)[MI][2 * NJB][4], int lane,
                                           int wm, int wn,
                                           uint32_t abase, uint32_t bbase)
{
    #pragma unroll
    for (int kk = 0; kk < 4; kk++) {
        uint32_t a[MI][4];
        #pragma unroll
        for (int mi = 0; mi < MI; mi++) {
            int row = wm + mi * 16 + (lane & 15);
            int k16 = 2 * kk + (lane >> 4);
            ldsm4(a[mi][0], a[mi][1], a[mi][2], a[mi][3],
                  abase + row * 128 + ((k16 ^ (row & 7)) << 4));
        }
        #pragma unroll
        for (int jb = 0; jb < NJB; jb++) {
            uint32_t b[4];
            int row = wn + jb * 16 + (lane & 7) + ((lane >> 4) << 3);
            int k16 = 2 * kk + ((lane >> 3) & 1);
            ldsm4(b[0], b[1], b[2], b[3],
                  bbase + row * 128 + ((k16 ^ (row & 7)) << 4));
            #pragma unroll
            for (int mi = 0; mi < MI; mi++) {
                mma16816h(acc[mi][jb * 2 + 0], a[mi][0], a[mi][1], a[mi][2], a[mi][3], b[0], b[1]);
                mma16816h(acc[mi][jb * 2 + 1], a[mi][0], a[mi][1], a[mi][2], a[mi][3], b[2], b[3]);
            }
        }
    }
}

// ---------------------------------------------------------------------------
// GEMM-O MMA. A either row-major [m=128][k=64] (128 B rows) or TRANSPOSED:
// mirrored U stored as TWO [k=64][m=64] sub-tiles (m-half h at +h*8192,
// 128 B rows), consumed via ldmatrix.x4.trans:
//   srow = kk*16 + 8*(lane>>4) + (lane&7)
//   cg   = ((m_off & 63) >> 3) + ((lane>>3)&1),  base += (m_off>>6)*8192
// ---------------------------------------------------------------------------
template<int MI, int NJB>
__device__ __forceinline__ void tile_mma_o(float (&acc)[MI][2 * NJB][4], int lane,
                                           int wm, int wn,
                                           uint32_t abase, uint32_t bbase, int trans)
{
    #pragma unroll
    for (int kk = 0; kk < 4; kk++) {
        uint32_t a[MI][4];
        if (!trans) {
            #pragma unroll
            for (int mi = 0; mi < MI; mi++) {
                int row = wm + mi * 16 + (lane & 15);
                int k16 = 2 * kk + (lane >> 4);
                ldsm4(a[mi][0], a[mi][1], a[mi][2], a[mi][3],
                      abase + row * 128 + ((k16 ^ (row & 7)) << 4));
            }
        } else {
            #pragma unroll
            for (int mi = 0; mi < MI; mi++) {
                int m_off = wm + mi * 16;
                uint32_t mh = (uint32_t)(m_off >> 6) * 8192u;
                int srow = kk * 16 + ((lane >> 4) << 3) + (lane & 7);
                int cg = ((m_off & 63) >> 3) + ((lane >> 3) & 1);
                ldsm4t(a[mi][0], a[mi][1], a[mi][2], a[mi][3],
                       abase + mh + srow * 128 + ((cg ^ (srow & 7)) << 4));
            }
        }
        #pragma unroll
        for (int jb = 0; jb < NJB; jb++) {
            uint32_t b[4];
            int row = wn + jb * 16 + (lane & 7) + ((lane >> 4) << 3);
            int k16 = 2 * kk + ((lane >> 3) & 1);
            ldsm4(b[0], b[1], b[2], b[3],
                  bbase + row * 128 + ((k16 ^ (row & 7)) << 4));
            #pragma unroll
            for (int mi = 0; mi < MI; mi++) {
                mma16816h(acc[mi][jb * 2 + 0], a[mi][0], a[mi][1], a[mi][2], a[mi][3], b[0], b[1]);
                mma16816h(acc[mi][jb * 2 + 1], a[mi][0], a[mi][1], a[mi][2], a[mi][3], b[2], b[3]);
            }
        }
    }
}

// ---------------------------------------------------------------------------
// K3: symmetric GEMM-S (triangular grid, 2080 CTAs) + fused exp epilogue.
// 2-stage cp.async, SINGLE barrier per iteration:
//   [cp_wait<0> ; barrier ; issue load(it+1) ; mma(it)]
// Safe: load target stage (it+1)%2 was last read by mma(it-1), which precedes
// barrier(it) in every warp. Stores ONLY the upper-tri U tile.
// ---------------------------------------------------------------------------
#define SMSTAGE 32768

__device__ __forceinline__ void s_load(size_t k0, int bm0, int bn0, int tid,
                                       uint32_t stbase)
{
    uint32_t abase = stbase, bbase = stbase + 16384;
    #pragma unroll
    for (int q = 0; q < 4; q++) {
        int v = tid + q * 256;
        int row = v >> 3, k16 = v & 7;
        uint32_t off = row * 128 + ((k16 ^ (row & 7)) << 4);
        cp16(abase + off, g_Eh + (size_t)(bm0 + row) * DIM + k0 + k16 * 8);
        cp16(bbase + off, g_Eh + (size_t)(bn0 + row) * DIM + k0 + k16 * 8);
    }
    cp_commit();
}

__global__ __launch_bounds__(256, 2) void k_gemm_s()
{
    extern __shared__ __align__(1024) char dsm[];
    uint32_t dynb = smem_u32(dsm);
    int tid = threadIdx.x, lane = tid & 31, wid = tid >> 5;
    int wm = (wid >> 2) * 64, wn = (wid & 3) * 32;

    // triangular decode: t -> (i <= j)
    int t = blockIdx.x;
    int j = (int)((sqrtf(8.0f * (float)t + 1.0f) - 1.0f) * 0.5f);
    while ((j + 1) * (j + 2) / 2 <= t) j++;
    while (j * (j + 1) / 2 > t) j--;
    int i = t - j * (j + 1) / 2;
    int bm0 = i * 128, bn0 = j * 128;

    float acc[4][4][4];
    #pragma unroll
    for (int a = 0; a < 4; a++)
        #pragma unroll
        for (int b = 0; b < 4; b++)
            #pragma unroll
            for (int q = 0; q < 4; q++) acc[a][b][q] = 0.0f;

    const int NIT = 4;   // 4 chunks of 64 = K 256
    s_load(0, bm0, bn0, tid, dynb);
    for (int it = 0; it < NIT; it++) {
        int s = it & 1;
        cp_wait<0>();
        __syncthreads();
        if (it + 1 < NIT)
            s_load((size_t)(it + 1) * 64, bm0, bn0, tid,
                   dynb + ((it + 1) & 1) * SMSTAGE);
        uint32_t base = dynb + s * SMSTAGE;
        tile_mma_t<4, 2>(acc, lane, wm, wn, base, base + 16384);
    }
    __syncthreads();   // epilogue reuses smem

    // ---- epilogue: U = exp(W - 3) ----
    int g = lane >> 2, c2 = (lane & 3) * 2;

    float pa[4], pb[4];
    #pragma unroll
    for (int mi = 0; mi < 4; mi++) { pa[mi] = 0.0f; pb[mi] = 0.0f; }
    #pragma unroll
    for (int mi = 0; mi < 4; mi++)
        #pragma unroll
        for (int nj = 0; nj < 4; nj++) {
            #pragma unroll
            for (int q = 0; q < 4; q++)
                acc[mi][nj][q] = fast_exp(acc[mi][nj][q] - 3.0f);
            pa[mi] += acc[mi][nj][0] + acc[mi][nj][1];
            pb[mi] += acc[mi][nj][2] + acc[mi][nj][3];
        }

    float* ssum = (float*)dsm;                    // [4][128]
    float* scol = (float*)(dsm + 2048);           // [2][128]
    #pragma unroll
    for (int mi = 0; mi < 4; mi++) {
        pa[mi] += __shfl_xor_sync(0xFFFFFFFFu, pa[mi], 1);
        pa[mi] += __shfl_xor_sync(0xFFFFFFFFu, pa[mi], 2);
        pb[mi] += __shfl_xor_sync(0xFFFFFFFFu, pb[mi], 1);
        pb[mi] += __shfl_xor_sync(0xFFFFFFFFu, pb[mi], 2);
        if ((lane & 3) == 0) {
            int rl = wm + mi * 16 + g;
            ssum[(wid & 3) * 128 + rl]     = pa[mi];
            ssum[(wid & 3) * 128 + rl + 8] = pb[mi];
        }
    }
    if (i != j) {
        float cs0[4], cs1[4];
        #pragma unroll
        for (int nj = 0; nj < 4; nj++) {
            cs0[nj] = 0.0f; cs1[nj] = 0.0f;
            #pragma unroll
            for (int mi = 0; mi < 4; mi++) {
                cs0[nj] += acc[mi][nj][0] + acc[mi][nj][2];
                cs1[nj] += acc[mi][nj][1] + acc[mi][nj][3];
            }
            #pragma unroll
            for (int o = 4; o <= 16; o <<= 1) {
                cs0[nj] += __shfl_xor_sync(0xFFFFFFFFu, cs0[nj], o);
                cs1[nj] += __shfl_xor_sync(0xFFFFFFFFu, cs1[nj], o);
            }
        }
        if (lane < 4) {
            #pragma unroll
            for (int nj = 0; nj < 4; nj++) {
                int col = wn + nj * 8 + lane * 2;
                scol[(wid >> 2) * 128 + col]     = cs0[nj];
                scol[(wid >> 2) * 128 + col + 1] = cs1[nj];
            }
        }
    }
    __syncthreads();
    if (tid < 128) {
        g_psum[(size_t)j * NROW + bm0 + tid] =
            ssum[tid] + ssum[128 + tid] + ssum[256 + tid] + ssum[384 + tid];
        if (i != j)
            g_psum[(size_t)i * NROW + bn0 + tid] = scol[tid] + scol[128 + tid];
    }
    __syncthreads();

    // row-major U tile store (smem-staged, coalesced) — upper triangle only.
    __half* s16 = (__half*)dsm;
    #pragma unroll
    for (int mi = 0; mi < 4; mi++)
        #pragma unroll
        for (int nj = 0; nj < 4; nj++) {
            int rl = wm + mi * 16 + g, col = wn + nj * 8 + c2;
            *(__half2*)&s16[rl * 136 + col] =
                __floats2half2_rn(acc[mi][nj][0], acc[mi][nj][1]);
            *(__half2*)&s16[(rl + 8) * 136 + col] =
                __floats2half2_rn(acc[mi][nj][2], acc[mi][nj][3]);
        }
    __syncthreads();
    {
        int rr = tid >> 1, hh = tid & 1;
        #pragma unroll
        for (int jb = 0; jb < 8; jb++) {
            uint4 v = *(uint4*)&s16[rr * 136 + hh * 64 + jb * 8];
            *(uint4*)&g_U[(size_t)(bm0 + rr) * NROW + bn0 + hh * 64 + jb * 8] = v;
        }
    }
}

// ---------------------------------------------------------------------------
// K5: O-partials, split-K x2, n-split x2.
// Grid (2, 64, 2) = 256 CTAs of 128 threads. CTA tile 128(m) x 128(n).
// 4 warps of 64x64. 3-stage x 32KB, SINGLE barrier per iteration:
//   [cp_wait<1> ; barrier ; issue load(it+2) ; mma(it)]
// Safe: stage (it+2)%3 was last read by mma(it-1) < barrier(it) in all warps.
// Mirror (trans) read for lower-tri k-blocks (two [64k][64m] sub-tiles).
// ---------------------------------------------------------------------------
#define OSTG 32768

__device__ __forceinline__ void o_load(size_t k0, int bm0, int bn0, int tid,
                                       uint32_t base, int trans)
{
    if (trans) {
        #pragma unroll
        for (int q = 0; q < 8; q++) {
            int v = tid + q * 128;                  // 0..1023
            uint32_t mh  = (uint32_t)(v >> 9);      // m-half 0/1
            int within   = v & 511;
            int row      = within >> 3;             // k row 0..63
            int k16      = within & 7;              // m 16B group within half
            uint32_t off = mh * 8192 + row * 128 + ((k16 ^ (row & 7)) << 4);
            cp16(base + off,
                 g_U + (k0 + row) * NROW + bm0 + mh * 64 + k16 * 8);
            int vrow = v >> 3, vk = v & 7;
            cp16(base + 16384 + vrow * 128 + ((vk ^ (vrow & 7)) << 4),
                 g_Vt + (size_t)(bn0 + vrow) * NROW + k0 + vk * 8);
        }
    } else {
        #pragma unroll
        for (int q = 0; q < 8; q++) {
            int v = tid + q * 128;
            int row = v >> 3, k16 = v & 7;
            uint32_t off = row * 128 + ((k16 ^ (row & 7)) << 4);
            cp16(base + off, g_U + (size_t)(bm0 + row) * NROW + k0 + k16 * 8);
            cp16(base + 16384 + off,
                 g_Vt + (size_t)(bn0 + row) * NROW + k0 + k16 * 8);
        }
    }
    cp_commit();
}

__global__ __launch_bounds__(128, 2) void k_gemm_o()
{
    extern __shared__ __align__(1024) char dsm[];
    uint32_t dynb = smem_u32(dsm);
    int tid = threadIdx.x, lane = tid & 31, wid = tid >> 5;
    int wm = (wid >> 1) * 64, wn = (wid & 1) * 64;
    int bm0 = blockIdx.y * 128;
    int bn0 = blockIdx.z * 128;
    size_t kbase = (size_t)blockIdx.x * 4096;
    float* Opar = g_Opar[blockIdx.x];
    int ib = bm0 >> 7;

    float acc[4][8][4];
    #pragma unroll
    for (int a = 0; a < 4; a++)
        #pragma unroll
        for (int b = 0; b < 8; b++)
            #pragma unroll
            for (int q = 0; q < 4; q++) acc[a][b][q] = 0.0f;

    const int NIT = 64;   // K half = 4096 in chunks of 64
    {
        int tr0 = ((int)(kbase >> 7)) < ib;
        o_load(kbase, bm0, bn0, tid, dynb, tr0);
        size_t k1 = kbase + 64;
        o_load(k1, bm0, bn0, tid, dynb + OSTG, ((int)(k1 >> 7)) < ib);
    }

    #pragma unroll 1
    for (int it = 0; it < NIT; it++) {
        int s = it % 3;
        size_t k0 = kbase + (size_t)it * 64;
        int trans = ((int)(k0 >> 7)) < ib;
        if (it + 1 < NIT) cp_wait<1>();
        else              cp_wait<0>();
        __syncthreads();
        if (it + 2 < NIT) {
            size_t kn = kbase + (size_t)(it + 2) * 64;
            o_load(kn, bm0, bn0, tid, dynb + ((it + 2) % 3) * OSTG,
                   ((int)(kn >> 7)) < ib);
        }
        uint32_t base = dynb + s * OSTG;
        tile_mma_o<4, 4>(acc, lane, wm, wn, base, base + 16384, trans);
    }

    int g = lane >> 2, c2 = (lane & 3) * 2;
    #pragma unroll
    for (int mi = 0; mi < 4; mi++) {
        int ra = bm0 + wm + mi * 16 + g;
        #pragma unroll
        for (int nj = 0; nj < 8; nj++) {
            int col = bn0 + wn + nj * 8 + c2;
            *(float2*)&Opar[(size_t)ra * DIM + col] =
                make_float2(acc[mi][nj][0], acc[mi][nj][1]);
            *(float2*)&Opar[(size_t)(ra + 8) * DIM + col] =
                make_float2(acc[mi][nj][2], acc[mi][nj][3]);
        }
    }
}

// ---------------------------------------------------------------------------
// K6: O = (Opar0 + Opar1) / rowsum.  Block = 4 rows; reduces the 64 psum
// partials per row in-block.
// ---------------------------------------------------------------------------
__global__ __launch_bounds__(256) void k_combine(float* __restrict__ C)
{
    __shared__ float sred[8];
    __shared__ float srinv[4];
    int t = threadIdx.x;
    int rowbase = blockIdx.x * 4;

    float p = g_psum[(size_t)(t & 63) * NROW + rowbase + (t >> 6)];
    #pragma unroll
    for (int o = 16; o; o >>= 1) p += __shfl_xor_sync(0xFFFFFFFFu, p, o);
    if ((t & 31) == 0) sred[t >> 5] = p;
    __syncthreads();
    if (t < 4) srinv[t] = 1.0f / (sred[2 * t] + sred[2 * t + 1]);
    __syncthreads();

    size_t idx = (size_t)blockIdx.x * 256 + t;     // float4 index
    float4 a = ((const float4*)g_Opar[0])[idx];
    float4 b = ((const float4*)g_Opar[1])[idx];
    float r = srinv[t >> 6];
    ((float4*)C)[idx] = make_float4((a.x + b.x) * r, (a.y + b.y) * r,
                                    (a.z + b.z) * r, (a.w + b.w) * r);
}

// ---------------------------------------------------------------------------
extern "C" void kernel_launch(void* const* d_in, const int* in_sizes, int n_in,
                              void* d_out, int out_size)
{
    const float* emb = (const float*)d_in[0];
    float* out = (float*)d_out;

    cudaFuncSetAttribute(k_gemm_s, cudaFuncAttributeMaxDynamicSharedMemorySize, 2 * SMSTAGE);
    cudaFuncSetAttribute(k_gemm_o, cudaFuncAttributeMaxDynamicSharedMemorySize, 3 * OSTG);

    k_normalize<<<NROW / 4, 128>>>(emb);

    dim3 tb(32, 8);
    k_transpose<<<dim3(NROW / 32, DIM / 32), tb>>>(emb);

    k_gemm_s<<<2080, 256, 2 * SMSTAGE>>>();

    k_gemm_o<<<dim3(2, NROW / 128, 2), 128, 3 * OSTG>>>();

    k_combine<<<NROW / 4, 256>>>(out);
}

// round 14
// speedup vs baseline: 1.0590x; 1.0108x over previous
#include <cuda_runtime.h>
#include <cuda_fp16.h>
#include <math.h>
#include <stdint.h>

#define NROW 8192
#define DIM  256

// ---------------- scratch (no cudaMalloc allowed) ----------------
static __device__ __half g_U   [(size_t)NROW * NROW];   // upper-tri tiles of exp(W-3)
static __device__ float  g_psum[(size_t)64 * NROW];     // per-colblock row sums
static __device__ __half g_Eh  [(size_t)NROW * DIM];    // normalized emb / sqrt(sigma)
static __device__ __half g_Vt  [(size_t)DIM * NROW];    // emb_org^T
static __device__ float  g_Opar[2][(size_t)NROW * DIM]; // split-K partial O

// ---------------- portable PTX helpers (sm_80+ only) ----------------
__device__ __forceinline__ uint32_t smem_u32(const void* p) {
    return (uint32_t)__cvta_generic_to_shared(p);
}
__device__ __forceinline__ void cp16(uint32_t dst, const void* src) {
    asm volatile("cp.async.cg.shared.global [%0], [%1], 16;"
                 :: "r"(dst), "l"(src) : "memory");
}
__device__ __forceinline__ void cp_commit() {
    asm volatile("cp.async.commit_group;" ::: "memory");
}
template <int N> __device__ __forceinline__ void cp_wait() {
    asm volatile("cp.async.wait_group %0;" :: "n"(N) : "memory");
}
__device__ __forceinline__ void ldsm4(uint32_t& r0, uint32_t& r1,
                                      uint32_t& r2, uint32_t& r3, uint32_t addr) {
    asm volatile("ldmatrix.sync.aligned.m8n8.x4.shared.b16 {%0,%1,%2,%3}, [%4];"
                 : "=r"(r0), "=r"(r1), "=r"(r2), "=r"(r3) : "r"(addr));
}
__device__ __forceinline__ void ldsm4t(uint32_t& r0, uint32_t& r1,
                                       uint32_t& r2, uint32_t& r3, uint32_t addr) {
    asm volatile("ldmatrix.sync.aligned.m8n8.x4.trans.shared.b16 {%0,%1,%2,%3}, [%4];"
                 : "=r"(r0), "=r"(r1), "=r"(r2), "=r"(r3) : "r"(addr));
}
__device__ __forceinline__ void mma16816h(float* d,
                                          uint32_t a0, uint32_t a1, uint32_t a2, uint32_t a3,
                                          uint32_t b0, uint32_t b1) {
    asm volatile("mma.sync.aligned.m16n8k16.row.col.f32.f16.f16.f32 "
                 "{%0,%1,%2,%3},{%4,%5,%6,%7},{%8,%9},{%0,%1,%2,%3};"
                 : "+f"(d[0]), "+f"(d[1]), "+f"(d[2]), "+f"(d[3])
                 : "r"(a0), "r"(a1), "r"(a2), "r"(a3), "r"(b0), "r"(b1));
}

// fast exp on the FMA pipe (avoids MUFU.EX2 wall at 67M exps).
__device__ __forceinline__ float fast_exp(float x)
{
    float t = x * 1.4426950408889634f;
    t = fmaxf(t, -126.0f);
    float fi = floorf(t);
    float f  = t - fi;
    float p = 1.5403530393381608e-4f;
    p = fmaf(p, f, 1.3333558146428443e-3f);
    p = fmaf(p, f, 9.6181291076284770e-3f);
    p = fmaf(p, f, 5.5504108664821580e-2f);
    p = fmaf(p, f, 2.4022650695910070e-1f);
    p = fmaf(p, f, 6.9314718055994530e-1f);
    p = fmaf(p, f, 1.0f);
    return p * __int_as_float(((int)fi + 127) << 23);
}

// ---------------------------------------------------------------------------
// K1 (fused): one pass over emb -> Eh (normalized fp16) AND Vt (transposed
// fp16). Block = 32 rows x 256 cols staged in smem (stride 257: conflict-free
// for row-wise, column-wise, and strided accesses).
// ---------------------------------------------------------------------------
__global__ __launch_bounds__(256) void k_prep(const float* __restrict__ emb)
{
    __shared__ float sm[32 * 257];
    __shared__ float sscale[32];
    int tid = threadIdx.x;
    int r0 = blockIdx.x * 32;

    // phase A: coalesced load of 32 full rows
    #pragma unroll
    for (int q = 0; q < 32; q++) {
        int v = tid + q * 256;
        int row = v >> 8, col = v & 255;
        sm[row * 257 + col] = emb[(size_t)(r0 + row) * DIM + col];
    }
    __syncthreads();

    // phase B: per-row L2 norm (8 lanes per row), fold 1/sqrt(sigma)
    {
        int w = tid >> 5, lane = tid & 31;
        int row = w * 4 + (lane >> 3);
        int l8 = lane & 7;
        float s = 0.0f;
        #pragma unroll
        for (int k = 0; k < 32; k++) {
            float x = sm[row * 257 + l8 + k * 8];
            s = fmaf(x, x, s);
        }
        s += __shfl_xor_sync(0xFFFFFFFFu, s, 1);
        s += __shfl_xor_sync(0xFFFFFFFFu, s, 2);
        s += __shfl_xor_sync(0xFFFFFFFFu, s, 4);
        if (l8 == 0)
            sscale[row] = 1.0f / (fmaxf(sqrtf(s), 1e-12f) * 0.316227766016838f);
    }
    __syncthreads();

    // phase C: Eh = row * scale (coalesced fp16 row-major)
    #pragma unroll
    for (int q = 0; q < 32; q++) {
        int v = tid + q * 256;
        int row = v >> 8, col = v & 255;
        g_Eh[(size_t)(r0 + row) * DIM + col] =
            __float2half(sm[row * 257 + col] * sscale[row]);
    }
    // phase D: Vt[c][r0+r] = emb[r][c] (transposed, 64B-coalesced; smem
    // column reads conflict-free via stride 257)
    #pragma unroll
    for (int q = 0; q < 32; q++) {
        int v = tid + q * 256;
        int c = v >> 5, r = v & 31;
        g_Vt[(size_t)c * NROW + r0 + r] = __float2half(sm[r * 257 + c]);
    }
}

// ---------------------------------------------------------------------------
// Shared MMA (A row-major in smem): warp tile (MI*16) x (NJB*16), k-chunk 64.
// ---------------------------------------------------------------------------
template<int MI, int NJB>
__device__ __forceinline__ void tile_mma_t(float (&acc)[MI][2 * NJB][4], int lane,
                                           int wm, int wn,
                                           uint32_t abase, uint32_t bbase)
{
    #pragma unroll
    for (int kk = 0; kk < 4; kk++) {
        uint32_t a[MI][4];
        #pragma unroll
        for (int mi = 0; mi < MI; mi++) {
            int row = wm + mi * 16 + (lane & 15);
            int k16 = 2 * kk + (lane >> 4);
            ldsm4(a[mi][0], a[mi][1], a[mi][2], a[mi][3],
                  abase + row * 128 + ((k16 ^ (row & 7)) << 4));
        }
        #pragma unroll
        for (int jb = 0; jb < NJB; jb++) {
            uint32_t b[4];
            int row = wn + jb * 16 + (lane & 7) + ((lane >> 4) << 3);
            int k16 = 2 * kk + ((lane >> 3) & 1);
            ldsm4(b[0], b[1], b[2], b[3],
                  bbase + row * 128 + ((k16 ^ (row & 7)) << 4));
            #pragma unroll
            for (int mi = 0; mi < MI; mi++) {
                mma16816h(acc[mi][jb * 2 + 0], a[mi][0], a[mi][1], a[mi][2], a[mi][3], b[0], b[1]);
                mma16816h(acc[mi][jb * 2 + 1], a[mi][0], a[mi][1], a[mi][2], a[mi][3], b[2], b[3]);
            }
        }
    }
}

// ---------------------------------------------------------------------------
// GEMM-O MMA. A either row-major [m=128][k=64] (128 B rows) or TRANSPOSED:
// mirrored U stored as TWO [k=64][m=64] sub-tiles (m-half h at +h*8192).
// ---------------------------------------------------------------------------
template<int MI, int NJB>
__device__ __forceinline__ void tile_mma_o(float (&acc)[MI][2 * NJB][4], int lane,
                                           int wm, int wn,
                                           uint32_t abase, uint32_t bbase, int trans)
{
    #pragma unroll
    for (int kk = 0; kk < 4; kk++) {
        uint32_t a[MI][4];
        if (!trans) {
            #pragma unroll
            for (int mi = 0; mi < MI; mi++) {
                int row = wm + mi * 16 + (lane & 15);
                int k16 = 2 * kk + (lane >> 4);
                ldsm4(a[mi][0], a[mi][1], a[mi][2], a[mi][3],
                      abase + row * 128 + ((k16 ^ (row & 7)) << 4));
            }
        } else {
            #pragma unroll
            for (int mi = 0; mi < MI; mi++) {
                int m_off = wm + mi * 16;
                uint32_t mh = (uint32_t)(m_off >> 6) * 8192u;
                int srow = kk * 16 + ((lane >> 4) << 3) + (lane & 7);
                int cg = ((m_off & 63) >> 3) + ((lane >> 3) & 1);
                ldsm4t(a[mi][0], a[mi][1], a[mi][2], a[mi][3],
                       abase + mh + srow * 128 + ((cg ^ (srow & 7)) << 4));
            }
        }
        #pragma unroll
        for (int jb = 0; jb < NJB; jb++) {
            uint32_t b[4];
            int row = wn + jb * 16 + (lane & 7) + ((lane >> 4) << 3);
            int k16 = 2 * kk + ((lane >> 3) & 1);
            ldsm4(b[0], b[1], b[2], b[3],
                  bbase + row * 128 + ((k16 ^ (row & 7)) << 4));
            #pragma unroll
            for (int mi = 0; mi < MI; mi++) {
                mma16816h(acc[mi][jb * 2 + 0], a[mi][0], a[mi][1], a[mi][2], a[mi][3], b[0], b[1]);
                mma16816h(acc[mi][jb * 2 + 1], a[mi][0], a[mi][1], a[mi][2], a[mi][3], b[2], b[3]);
            }
        }
    }
}

// ---------------------------------------------------------------------------
// K3: symmetric GEMM-S (triangular grid, 2080 CTAs) + fused exp epilogue.
// 2-stage cp.async, single barrier per iteration. Upper-tri U only.
// ---------------------------------------------------------------------------
#define SMSTAGE 32768

__device__ __forceinline__ void s_load(size_t k0, int bm0, int bn0, int tid,
                                       uint32_t stbase)
{
    uint32_t abase = stbase, bbase = stbase + 16384;
    #pragma unroll
    for (int q = 0; q < 4; q++) {
        int v = tid + q * 256;
        int row = v >> 3, k16 = v & 7;
        uint32_t off = row * 128 + ((k16 ^ (row & 7)) << 4);
        cp16(abase + off, g_Eh + (size_t)(bm0 + row) * DIM + k0 + k16 * 8);
        cp16(bbase + off, g_Eh + (size_t)(bn0 + row) * DIM + k0 + k16 * 8);
    }
    cp_commit();
}

__global__ __launch_bounds__(256, 2) void k_gemm_s()
{
    extern __shared__ __align__(1024) char dsm[];
    uint32_t dynb = smem_u32(dsm);
    int tid = threadIdx.x, lane = tid & 31, wid = tid >> 5;
    int wm = (wid >> 2) * 64, wn = (wid & 3) * 32;

    // triangular decode: t -> (i <= j)
    int t = blockIdx.x;
    int j = (int)((sqrtf(8.0f * (float)t + 1.0f) - 1.0f) * 0.5f);
    while ((j + 1) * (j + 2) / 2 <= t) j++;
    while (j * (j + 1) / 2 > t) j--;
    int i = t - j * (j + 1) / 2;
    int bm0 = i * 128, bn0 = j * 128;

    float acc[4][4][4];
    #pragma unroll
    for (int a = 0; a < 4; a++)
        #pragma unroll
        for (int b = 0; b < 4; b++)
            #pragma unroll
            for (int q = 0; q < 4; q++) acc[a][b][q] = 0.0f;

    const int NIT = 4;   // 4 chunks of 64 = K 256
    s_load(0, bm0, bn0, tid, dynb);
    for (int it = 0; it < NIT; it++) {
        int s = it & 1;
        cp_wait<0>();
        __syncthreads();
        if (it + 1 < NIT)
            s_load((size_t)(it + 1) * 64, bm0, bn0, tid,
                   dynb + ((it + 1) & 1) * SMSTAGE);
        uint32_t base = dynb + s * SMSTAGE;
        tile_mma_t<4, 2>(acc, lane, wm, wn, base, base + 16384);
    }
    __syncthreads();   // epilogue reuses smem

    // ---- epilogue: U = exp(W - 3) ----
    int g = lane >> 2, c2 = (lane & 3) * 2;

    float pa[4], pb[4];
    #pragma unroll
    for (int mi = 0; mi < 4; mi++) { pa[mi] = 0.0f; pb[mi] = 0.0f; }
    #pragma unroll
    for (int mi = 0; mi < 4; mi++)
        #pragma unroll
        for (int nj = 0; nj < 4; nj++) {
            #pragma unroll
            for (int q = 0; q < 4; q++)
                acc[mi][nj][q] = fast_exp(acc[mi][nj][q] - 3.0f);
            pa[mi] += acc[mi][nj][0] + acc[mi][nj][1];
            pb[mi] += acc[mi][nj][2] + acc[mi][nj][3];
        }

    float* ssum = (float*)dsm;                    // [4][128]
    float* scol = (float*)(dsm + 2048);           // [2][128]
    #pragma unroll
    for (int mi = 0; mi < 4; mi++) {
        pa[mi] += __shfl_xor_sync(0xFFFFFFFFu, pa[mi], 1);
        pa[mi] += __shfl_xor_sync(0xFFFFFFFFu, pa[mi], 2);
        pb[mi] += __shfl_xor_sync(0xFFFFFFFFu, pb[mi], 1);
        pb[mi] += __shfl_xor_sync(0xFFFFFFFFu, pb[mi], 2);
        if ((lane & 3) == 0) {
            int rl = wm + mi * 16 + g;
            ssum[(wid & 3) * 128 + rl]     = pa[mi];
            ssum[(wid & 3) * 128 + rl + 8] = pb[mi];
        }
    }
    if (i != j) {
        float cs0[4], cs1[4];
        #pragma unroll
        for (int nj = 0; nj < 4; nj++) {
            cs0[nj] = 0.0f; cs1[nj] = 0.0f;
            #pragma unroll
            for (int mi = 0; mi < 4; mi++) {
                cs0[nj] += acc[mi][nj][0] + acc[mi][nj][2];
                cs1[nj] += acc[mi][nj][1] + acc[mi][nj][3];
            }
            #pragma unroll
            for (int o = 4; o <= 16; o <<= 1) {
                cs0[nj] += __shfl_xor_sync(0xFFFFFFFFu, cs0[nj], o);
                cs1[nj] += __shfl_xor_sync(0xFFFFFFFFu, cs1[nj], o);
            }
        }
        if (lane < 4) {
            #pragma unroll
            for (int nj = 0; nj < 4; nj++) {
                int col = wn + nj * 8 + lane * 2;
                scol[(wid >> 2) * 128 + col]     = cs0[nj];
                scol[(wid >> 2) * 128 + col + 1] = cs1[nj];
            }
        }
    }
    __syncthreads();
    if (tid < 128) {
        g_psum[(size_t)j * NROW + bm0 + tid] =
            ssum[tid] + ssum[128 + tid] + ssum[256 + tid] + ssum[384 + tid];
        if (i != j)
            g_psum[(size_t)i * NROW + bn0 + tid] = scol[tid] + scol[128 + tid];
    }
    __syncthreads();

    // row-major U tile store (smem-staged, coalesced) — upper triangle only.
    __half* s16 = (__half*)dsm;
    #pragma unroll
    for (int mi = 0; mi < 4; mi++)
        #pragma unroll
        for (int nj = 0; nj < 4; nj++) {
            int rl = wm + mi * 16 + g, col = wn + nj * 8 + c2;
            *(__half2*)&s16[rl * 136 + col] =
                __floats2half2_rn(acc[mi][nj][0], acc[mi][nj][1]);
            *(__half2*)&s16[(rl + 8) * 136 + col] =
                __floats2half2_rn(acc[mi][nj][2], acc[mi][nj][3]);
        }
    __syncthreads();
    {
        int rr = tid >> 1, hh = tid & 1;
        #pragma unroll
        for (int jb = 0; jb < 8; jb++) {
            uint4 v = *(uint4*)&s16[rr * 136 + hh * 64 + jb * 8];
            *(uint4*)&g_U[(size_t)(bm0 + rr) * NROW + bn0 + hh * 64 + jb * 8] = v;
        }
    }
}

// ---------------------------------------------------------------------------
// K5: O-partials, split-K x2, n-split x2.
// Grid (2, 64, 2) = 256 CTAs of 128 threads. CTA tile 128(m) x 128(n).
// 4 warps of 64x64. 3-stage x 32KB, single barrier per iteration.
// Mirror (trans) read for lower-tri k-blocks (two [64k][64m] sub-tiles).
// ---------------------------------------------------------------------------
#define OSTG 32768

__device__ __forceinline__ void o_load(size_t k0, int bm0, int bn0, int tid,
                                       uint32_t base, int trans)
{
    if (trans) {
        #pragma unroll
        for (int q = 0; q < 8; q++) {
            int v = tid + q * 128;                  // 0..1023
            uint32_t mh  = (uint32_t)(v >> 9);      // m-half 0/1
            int within   = v & 511;
            int row      = within >> 3;             // k row 0..63
            int k16      = within & 7;              // m 16B group within half
            uint32_t off = mh * 8192 + row * 128 + ((k16 ^ (row & 7)) << 4);
            cp16(base + off,
                 g_U + (k0 + row) * NROW + bm0 + mh * 64 + k16 * 8);
            int vrow = v >> 3, vk = v & 7;
            cp16(base + 16384 + vrow * 128 + ((vk ^ (vrow & 7)) << 4),
                 g_Vt + (size_t)(bn0 + vrow) * NROW + k0 + vk * 8);
        }
    } else {
        #pragma unroll
        for (int q = 0; q < 8; q++) {
            int v = tid + q * 128;
            int row = v >> 3, k16 = v & 7;
            uint32_t off = row * 128 + ((k16 ^ (row & 7)) << 4);
            cp16(base + off, g_U + (size_t)(bm0 + row) * NROW + k0 + k16 * 8);
            cp16(base + 16384 + off,
                 g_Vt + (size_t)(bn0 + row) * NROW + k0 + k16 * 8);
        }
    }
    cp_commit();
}

__global__ __launch_bounds__(128, 2) void k_gemm_o()
{
    extern __shared__ __align__(1024) char dsm[];
    uint32_t dynb = smem_u32(dsm);
    int tid = threadIdx.x, lane = tid & 31, wid = tid >> 5;
    int wm = (wid >> 1) * 64, wn = (wid & 1) * 64;
    int bm0 = blockIdx.y * 128;
    int bn0 = blockIdx.z * 128;
    size_t kbase = (size_t)blockIdx.x * 4096;
    float* Opar = g_Opar[blockIdx.x];
    int ib = bm0 >> 7;

    float acc[4][8][4];
    #pragma unroll
    for (int a = 0; a < 4; a++)
        #pragma unroll
        for (int b = 0; b < 8; b++)
            #pragma unroll
            for (int q = 0; q < 4; q++) acc[a][b][q] = 0.0f;

    const int NIT = 64;   // K half = 4096 in chunks of 64
    {
        int tr0 = ((int)(kbase >> 7)) < ib;
        o_load(kbase, bm0, bn0, tid, dynb, tr0);
        size_t k1 = kbase + 64;
        o_load(k1, bm0, bn0, tid, dynb + OSTG, ((int)(k1 >> 7)) < ib);
    }

    #pragma unroll 1
    for (int it = 0; it < NIT; it++) {
        int s = it % 3;
        size_t k0 = kbase + (size_t)it * 64;
        int trans = ((int)(k0 >> 7)) < ib;
        if (it + 1 < NIT) cp_wait<1>();
        else              cp_wait<0>();
        __syncthreads();
        if (it + 2 < NIT) {
            size_t kn = kbase + (size_t)(it + 2) * 64;
            o_load(kn, bm0, bn0, tid, dynb + ((it + 2) % 3) * OSTG,
                   ((int)(kn >> 7)) < ib);
        }
        uint32_t base = dynb + s * OSTG;
        tile_mma_o<4, 4>(acc, lane, wm, wn, base, base + 16384, trans);
    }

    int g = lane >> 2, c2 = (lane & 3) * 2;
    #pragma unroll
    for (int mi = 0; mi < 4; mi++) {
        int ra = bm0 + wm + mi * 16 + g;
        #pragma unroll
        for (int nj = 0; nj < 8; nj++) {
            int col = bn0 + wn + nj * 8 + c2;
            *(float2*)&Opar[(size_t)ra * DIM + col] =
                make_float2(acc[mi][nj][0], acc[mi][nj][1]);
            *(float2*)&Opar[(size_t)(ra + 8) * DIM + col] =
                make_float2(acc[mi][nj][2], acc[mi][nj][3]);
        }
    }
}

// ---------------------------------------------------------------------------
// K6: O = (Opar0 + Opar1) / rowsum.  Block = 4 rows; reduces the 64 psum
// partials per row in-block.
// ---------------------------------------------------------------------------
__global__ __launch_bounds__(256) void k_combine(float* __restrict__ C)
{
    __shared__ float sred[8];
    __shared__ float srinv[4];
    int t = threadIdx.x;
    int rowbase = blockIdx.x * 4;

    float p = g_psum[(size_t)(t & 63) * NROW + rowbase + (t >> 6)];
    #pragma unroll
    for (int o = 16; o; o >>= 1) p += __shfl_xor_sync(0xFFFFFFFFu, p, o);
    if ((t & 31) == 0) sred[t >> 5] = p;
    __syncthreads();
    if (t < 4) srinv[t] = 1.0f / (sred[2 * t] + sred[2 * t + 1]);
    __syncthreads();

    size_t idx = (size_t)blockIdx.x * 256 + t;     // float4 index
    float4 a = ((const float4*)g_Opar[0])[idx];
    float4 b = ((const float4*)g_Opar[1])[idx];
    float r = srinv[t >> 6];
    ((float4*)C)[idx] = make_float4((a.x + b.x) * r, (a.y + b.y) * r,
                                    (a.z + b.z) * r, (a.w + b.w) * r);
}

// ---------------------------------------------------------------------------
extern "C" void kernel_launch(void* const* d_in, const int* in_sizes, int n_in,
                              void* d_out, int out_size)
{
    const float* emb = (const float*)d_in[0];
    float* out = (float*)d_out;

    cudaFuncSetAttribute(k_gemm_s, cudaFuncAttributeMaxDynamicSharedMemorySize, 2 * SMSTAGE);
    cudaFuncSetAttribute(k_gemm_o, cudaFuncAttributeMaxDynamicSharedMemorySize, 3 * OSTG);

    k_prep<<<NROW / 32, 256>>>(emb);

    k_gemm_s<<<2080, 256, 2 * SMSTAGE>>>();

    k_gemm_o<<<dim3(2, NROW / 128, 2), 128, 3 * OSTG>>>();

    k_combine<<<NROW / 4, 256>>>(out);
}